// round 10
// baseline (speedup 1.0000x reference)
#include <cuda_runtime.h>
#include <cuda_bf16.h>

// B = 8192 rows, T = 4096 features, G = 64 groups.
// Group sizes cycle (32, 64, 96, 64) x 16; all boundaries are multiples of 32,
// so each aligned 32-elem chunk belongs to exactly one group (128 chunks/row).
// Output: d_out[0..B) = Z (fp32), d_out[B..B+B*64) = a (fp32 row-major [B,64]).
//
// R10 = R8 split with a fixed epilogue kernel.
//  k1 (unchanged from R8, measured 5.87 TB/s effective): barrier-free stream,
//     chunk sums straight to gmem scratch. No smem, no __syncthreads.
//  k2 (fixed): 256 CTAs x 32 rows. Batch-load 16KB of chunk sums per CTA with
//     4 coalesced float4/thread (MLP=4), one barrier, then 8 warps x 4 rows
//     each run the R6 epilogue from smem. Was 6.2us (MLP=1, 1024 CTAs) -> ~1.5us.

#define T_DIM    4096
#define G_DIM    64
#define B_DIM    8192
#define NTHREADS 256
#define ROWS_K2  32

__device__ float g_chunks[B_DIM * 128];   // 4MB static scratch

// ---------------- kernel 1: barrier-free stream + chunk reduce ----------------
__global__ __launch_bounds__(NTHREADS, 8)
void agp_stream(const float* __restrict__ H)
{
    const int b   = blockIdx.x;
    const int tid = threadIdx.x;

    const float4* row4 = reinterpret_cast<const float4*>(H + (size_t)b * T_DIM);
    float* dst = g_chunks + (size_t)b * 128;

    #pragma unroll
    for (int k = 0; k < 4; ++k) {
        float4 v = row4[tid + NTHREADS * k];
        float s = (v.x + v.y) + (v.z + v.w);
        // aligned 8-lane butterfly -> 32-elem chunk sum in lanes 0,8,16,24
        s += __shfl_xor_sync(0xffffffffu, s, 1);
        s += __shfl_xor_sync(0xffffffffu, s, 2);
        s += __shfl_xor_sync(0xffffffffu, s, 4);
        if ((tid & 7) == 0)
            dst[(tid >> 3) + 32 * k] = s;
    }
}

// ---------------- kernel 2: chunks -> groups -> softmax -> Z ----------------
__global__ __launch_bounds__(NTHREADS, 8)
void agp_epilogue(const float* __restrict__ score_w,
                  const float* __restrict__ score_b,
                  float* __restrict__ out, int B)
{
    const int tid  = threadIdx.x;
    const int wid  = tid >> 5;
    const int lane = tid & 31;
    const int row0 = blockIdx.x * ROWS_K2;

    __shared__ float cs[ROWS_K2][128];   // 16KB

    // batch-load 32 rows x 128 chunks = 1024 float4, 4 per thread, MLP=4
    const float4* src = reinterpret_cast<const float4*>(g_chunks + (size_t)row0 * 128);
    float4* dstv = reinterpret_cast<float4*>(&cs[0][0]);
    #pragma unroll
    for (int k = 0; k < 4; ++k)
        dstv[tid + NTHREADS * k] = src[tid + NTHREADS * k];
    __syncthreads();

    const float w    = __ldg(score_w);
    const float bias = __ldg(score_b);

    // per-subgroup (g & 3): chunk start within 8-chunk cycle, count, 1/size
    const int   c_start[4] = {0, 1, 3, 6};
    const int   c_cnt[4]   = {1, 2, 3, 2};
    const float inv_sz[4]  = {1.0f/32.0f, 1.0f/64.0f, 1.0f/96.0f, 1.0f/64.0f};

    // each warp handles 4 consecutive local rows
    #pragma unroll 1
    for (int rr = 0; rr < 4; ++rr) {
        const int r = wid * 4 + rr;        // local row in smem
        const int b = row0 + r;            // global row

        float Gm[2], sc[2];
        #pragma unroll
        for (int j = 0; j < 2; ++j) {
            int g    = lane + 32 * j;
            int sub  = g & 3;
            int base = (g >> 2) * 8 + c_start[sub];
            float s = 0.0f;
            #pragma unroll
            for (int c = 0; c < 3; ++c)
                if (c < c_cnt[sub]) s += cs[r][base + c];
            Gm[j] = s * inv_sz[sub];
            sc[j] = Gm[j] * w + bias;
        }

        // max tree (required before exp)
        float mx = fmaxf(sc[0], sc[1]);
        #pragma unroll
        for (int d = 16; d > 0; d >>= 1)
            mx = fmaxf(mx, __shfl_xor_sync(0xffffffffu, mx, d));

        float p0 = __expf(sc[0] - mx);
        float p1 = __expf(sc[1] - mx);

        // interleaved independent trees: ssum = sum(p), pz = sum(p*G)
        float ssum = p0 + p1;
        float pz   = p0 * Gm[0] + p1 * Gm[1];
        #pragma unroll
        for (int d = 16; d > 0; d >>= 1) {
            ssum += __shfl_xor_sync(0xffffffffu, ssum, d);
            pz   += __shfl_xor_sync(0xffffffffu, pz, d);
        }
        float inv = 1.0f / ssum;

        float* a_out = out + B + (size_t)b * G_DIM;
        a_out[lane]      = p0 * inv;
        a_out[lane + 32] = p1 * inv;
        if (lane == 0) out[b] = pz * inv;   // Z = sum(a*G) = pz / ssum
    }
}

extern "C" void kernel_launch(void* const* d_in, const int* in_sizes, int n_in,
                              void* d_out, int out_size)
{
    const float* H  = (const float*)d_in[0];   // [B, 4096]
    const float* sw = (const float*)d_in[1];   // [1,1]
    const float* sb = (const float*)d_in[2];   // [1]
    float* out = (float*)d_out;

    int B = in_sizes[0] / T_DIM;               // 8192
    agp_stream<<<B, NTHREADS>>>(H);
    agp_epilogue<<<B / ROWS_K2, NTHREADS>>>(sw, sb, out, B);
}

// round 11
// speedup vs baseline: 1.0760x; 1.0760x over previous
#include <cuda_runtime.h>
#include <cuda_bf16.h>
#include <cstdint>

// B = 8192 rows, T = 4096 features, G = 64 groups.
// Group sizes cycle (32, 64, 96, 64) x 16; all boundaries are multiples of 32,
// so each aligned 32-elem chunk belongs to exactly one group (128 chunks/row).
// Output: d_out[0..B) = Z (fp32), d_out[B..B+B*64) = a (fp32 row-major [B,64]).
//
// R11: TMA BULK load path (UBLKCP). R6's exact shape (1 row/CTA, grid 8192,
// 256 thr, 8 CTA/SM) but the 16KB row arrives via ONE cp.async.bulk into smem:
//  - zero per-thread LDG issues -> no L1tex wavefront-queue contention
//  - zero registers spent on the load stream
//  - DRAM requests generated by the TMA engine, not warp scoreboards
// Reduce from smem (conflict-free LDS.128) + unchanged R6 epilogue.

#define T_DIM    4096
#define G_DIM    64
#define NTHREADS 256

__device__ __forceinline__ uint32_t smem_u32(const void* p) {
    return (uint32_t)__cvta_generic_to_shared(p);
}

__global__ __launch_bounds__(NTHREADS, 8)
void agp_kernel(const float* __restrict__ H,
                const float* __restrict__ score_w,
                const float* __restrict__ score_b,
                float* __restrict__ out, int B)
{
    const int b   = blockIdx.x;
    const int tid = threadIdx.x;

    __shared__ alignas(128) float tile[T_DIM];     // 16KB row buffer
    __shared__ float chunk_sum[T_DIM / 32];        // 128 chunk sums
    __shared__ alignas(8) uint64_t mbar;

    const uint32_t mbar_a = smem_u32(&mbar);

    if (tid == 0) {
        asm volatile("mbarrier.init.shared.b64 [%0], 1;" :: "r"(mbar_a) : "memory");
    }
    __syncthreads();

    if (tid == 0) {
        asm volatile("mbarrier.arrive.expect_tx.shared.b64 _, [%0], %1;"
                     :: "r"(mbar_a), "r"((uint32_t)(T_DIM * 4)) : "memory");
        asm volatile("cp.async.bulk.shared::cta.global.mbarrier::complete_tx::bytes "
                     "[%0], [%1], %2, [%3];"
                     :: "r"(smem_u32(tile)),
                        "l"(H + (size_t)b * T_DIM),
                        "r"((uint32_t)(T_DIM * 4)),
                        "r"(mbar_a)
                     : "memory");
    }

    // all threads wait for the bulk copy (phase 0; buffer used once)
    {
        uint32_t done;
        asm volatile(
            "{\n\t.reg .pred p;\n\t"
            "mbarrier.try_wait.parity.acquire.cta.shared::cta.b64 p, [%1], 0;\n\t"
            "selp.b32 %0, 1, 0, p;\n\t}"
            : "=r"(done) : "r"(mbar_a) : "memory");
        if (!done) {
            asm volatile(
                "{\n\t.reg .pred P1;\n\t"
                "W_%=:\n\t"
                "mbarrier.try_wait.parity.acquire.cta.shared::cta.b64 P1, [%0], 0, 0x989680;\n\t"
                "@P1 bra.uni D_%=;\n\t"
                "bra.uni W_%=;\n\t"
                "D_%=:\n\t}"
                :: "r"(mbar_a) : "memory");
        }
    }

    // --- Phase 1: reduce smem tile -> 128 chunk sums (conflict-free LDS.128) ---
    const float4* t4 = reinterpret_cast<const float4*>(tile);
    #pragma unroll
    for (int k = 0; k < 4; ++k) {
        float4 v = t4[tid + NTHREADS * k];
        float s = (v.x + v.y) + (v.z + v.w);
        // aligned 8-lane butterfly -> one 32-elem chunk sum
        s += __shfl_xor_sync(0xffffffffu, s, 1);
        s += __shfl_xor_sync(0xffffffffu, s, 2);
        s += __shfl_xor_sync(0xffffffffu, s, 4);
        if ((tid & 7) == 0)
            chunk_sum[(tid >> 3) + 32 * k] = s;
    }
    __syncthreads();

    // --- Phase 2: warp 0 does groups -> softmax -> Z (R6 epilogue) ---
    if (tid < 32) {
        const float w    = __ldg(score_w);
        const float bias = __ldg(score_b);

        const int   c_start[4] = {0, 1, 3, 6};
        const int   c_cnt[4]   = {1, 2, 3, 2};
        const float inv_sz[4]  = {1.0f/32.0f, 1.0f/64.0f, 1.0f/96.0f, 1.0f/64.0f};

        float Gm[2], sc[2];
        #pragma unroll
        for (int j = 0; j < 2; ++j) {
            int g    = tid + 32 * j;
            int sub  = g & 3;
            int base = (g >> 2) * 8 + c_start[sub];
            float s = 0.0f;
            #pragma unroll
            for (int c = 0; c < 3; ++c)
                if (c < c_cnt[sub]) s += chunk_sum[base + c];
            Gm[j] = s * inv_sz[sub];
            sc[j] = Gm[j] * w + bias;
        }

        float mx = fmaxf(sc[0], sc[1]);
        #pragma unroll
        for (int d = 16; d > 0; d >>= 1)
            mx = fmaxf(mx, __shfl_xor_sync(0xffffffffu, mx, d));

        float p0 = __expf(sc[0] - mx);
        float p1 = __expf(sc[1] - mx);

        float ssum = p0 + p1;
        float pz   = p0 * Gm[0] + p1 * Gm[1];
        #pragma unroll
        for (int d = 16; d > 0; d >>= 1) {
            ssum += __shfl_xor_sync(0xffffffffu, ssum, d);
            pz   += __shfl_xor_sync(0xffffffffu, pz, d);
        }
        float inv = 1.0f / ssum;

        float* a_out = out + B + (size_t)b * G_DIM;
        a_out[tid]      = p0 * inv;
        a_out[tid + 32] = p1 * inv;
        if (tid == 0) out[b] = pz * inv;   // Z = sum(a*G) = pz / ssum
    }
}

extern "C" void kernel_launch(void* const* d_in, const int* in_sizes, int n_in,
                              void* d_out, int out_size)
{
    const float* H  = (const float*)d_in[0];   // [B, 4096]
    const float* sw = (const float*)d_in[1];   // [1,1]
    const float* sb = (const float*)d_in[2];   // [1]
    float* out = (float*)d_out;

    int B = in_sizes[0] / T_DIM;               // 8192
    agp_kernel<<<B, NTHREADS>>>(H, sw, sb, out, B);
}